// round 1
// baseline (speedup 1.0000x reference)
#include <cuda_runtime.h>
#include <math.h>

#define NN 50000
#define EE 800000
#define FF 64
#define HH 128

// ---------------- scratch (no allocations allowed) ----------------
__device__ float g_buf0[NN * HH];
__device__ float g_buf1[NN * HH];
__device__ float g_buf2[NN * HH];
__device__ float g_dinv[NN];
__device__ int   g_deg[NN];
__device__ int   g_incl[NN];
__device__ int   g_rowptr[NN + 1];
__device__ int   g_cursor[NN];
__device__ int   g_col[EE];
__device__ int   g_bsum[64];
__device__ int   g_btop[64];

// ---------------- graph preprocessing ----------------
__global__ void k_init_deg(int* deg) {
    int i = blockIdx.x * blockDim.x + threadIdx.x;
    if (i < NN) deg[i] = 0;
}

__global__ void k_count(const int* __restrict__ ei, int* deg) {
    int e = blockIdx.x * blockDim.x + threadIdx.x;
    if (e < EE) atomicAdd(&deg[ei[EE + e]], 1);
}

__global__ void k_scan_block(const int* __restrict__ deg, int* incl, int* bsum) {
    __shared__ int s[1024];
    int i = blockIdx.x * 1024 + threadIdx.x;
    s[threadIdx.x] = (i < NN) ? deg[i] : 0;
    __syncthreads();
    for (int off = 1; off < 1024; off <<= 1) {
        int t = (threadIdx.x >= off) ? s[threadIdx.x - off] : 0;
        __syncthreads();
        s[threadIdx.x] += t;
        __syncthreads();
    }
    if (i < NN) incl[i] = s[threadIdx.x];
    if (threadIdx.x == 1023) bsum[blockIdx.x] = s[1023];
}

__global__ void k_scan_tops(const int* __restrict__ bsum, int* btop, int nb) {
    __shared__ int s[64];
    int t = threadIdx.x;
    s[t] = (t < nb) ? bsum[t] : 0;
    __syncthreads();
    for (int off = 1; off < 64; off <<= 1) {
        int v = (t >= off) ? s[t - off] : 0;
        __syncthreads();
        s[t] += v;
        __syncthreads();
    }
    btop[t] = s[t];
}

__global__ void k_finalize(const int* __restrict__ deg, const int* __restrict__ incl,
                           const int* __restrict__ btop,
                           int* rowptr, int* cursor, float* dinv) {
    int i = blockIdx.x * blockDim.x + threadIdx.x;
    if (i >= NN) return;
    int blk = i >> 10;
    int off = blk ? btop[blk - 1] : 0;
    int inc = incl[i] + off;
    int exc = inc - deg[i];
    rowptr[i] = exc;
    cursor[i] = exc;
    if (i == NN - 1) rowptr[NN] = inc;
    dinv[i] = rsqrtf((float)deg[i] + 1.0f);  // +1 for self-loop
}

__global__ void k_fill(const int* __restrict__ ei, int* cursor, int* col) {
    int e = blockIdx.x * blockDim.x + threadIdx.x;
    if (e >= EE) return;
    int s = ei[e];
    int d = ei[EE + e];
    int pos = atomicAdd(&cursor[d], 1);
    col[pos] = s;
}

// ---------------- GEMM: C[NN,NC] = A[NN,K] @ W[K,NC], fused epilogues ----------------
#define M_RELU 0   // relu(acc + bias)
#define M_BIAS 1   // acc + bias
#define M_DINV 2   // acc * dinv[row]   (no bias)
#define M_SIG  3   // sigmoid(acc + bias)

template <int K, int NC, int MODE>
__global__ void __launch_bounds__(NC * 2)
k_gemm(const float* __restrict__ A, const float* __restrict__ W,
       const float* __restrict__ bias, const float* __restrict__ dinv,
       float* __restrict__ C) {
    constexpr int BM = 64, BK = 64, TM = 4, TN = 8;
    constexpr int TX = NC / TN;          // 16 (NC=128) or 8 (NC=64)
    constexpr int NT = TX * (BM / TM);   // 256 or 128 threads

    __shared__ float Ws[BK][NC];
    __shared__ float As[BM][BK];

    const int tid = threadIdx.x;
    const int tx = tid % TX;
    const int ty = tid / TX;
    const int row0 = blockIdx.x * BM;

    float acc[TM][TN];
#pragma unroll
    for (int i = 0; i < TM; i++)
#pragma unroll
        for (int j = 0; j < TN; j++) acc[i][j] = 0.0f;

    for (int kk = 0; kk < K; kk += BK) {
        // stage W chunk [BK, NC]
#pragma unroll
        for (int i = tid * 4; i < BK * NC; i += NT * 4) {
            int r = i / NC, c = i % NC;
            *(float4*)&Ws[r][c] = *(const float4*)&W[(kk + r) * NC + c];
        }
        // stage A chunk [BM, BK]
#pragma unroll
        for (int i = tid * 4; i < BM * BK; i += NT * 4) {
            int r = i / BK, c = i % BK;
            int gr = row0 + r;
            float4 v = make_float4(0.f, 0.f, 0.f, 0.f);
            if (gr < NN) v = *(const float4*)&A[gr * K + kk + c];
            *(float4*)&As[r][c] = v;
        }
        __syncthreads();

#pragma unroll
        for (int k = 0; k < BK; k++) {
            float a[TM];
#pragma unroll
            for (int i = 0; i < TM; i++) a[i] = As[ty * TM + i][k];
            float4 w0 = *(float4*)&Ws[k][tx * TN];
            float4 w1 = *(float4*)&Ws[k][tx * TN + 4];
            float w[TN] = {w0.x, w0.y, w0.z, w0.w, w1.x, w1.y, w1.z, w1.w};
#pragma unroll
            for (int i = 0; i < TM; i++)
#pragma unroll
                for (int j = 0; j < TN; j++) acc[i][j] = fmaf(a[i], w[j], acc[i][j]);
        }
        __syncthreads();
    }

    // epilogue
    float b[TN];
    if (MODE != M_DINV) {
#pragma unroll
        for (int j = 0; j < TN; j++) b[j] = bias[tx * TN + j];
    }
#pragma unroll
    for (int i = 0; i < TM; i++) {
        int gr = row0 + ty * TM + i;
        if (gr >= NN) break;
        float dn = (MODE == M_DINV) ? dinv[gr] : 0.0f;
        float o[TN];
#pragma unroll
        for (int j = 0; j < TN; j++) {
            float v = acc[i][j];
            if (MODE == M_RELU)      v = fmaxf(v + b[j], 0.0f);
            else if (MODE == M_BIAS) v = v + b[j];
            else if (MODE == M_DINV) v = v * dn;
            else                     v = 1.0f / (1.0f + expf(-(v + b[j])));
            o[j] = v;
        }
        float4* cp = (float4*)&C[gr * NC + tx * TN];
        cp[0] = make_float4(o[0], o[1], o[2], o[3]);
        cp[1] = make_float4(o[4], o[5], o[6], o[7]);
    }
}

// ---------------- CSR gather-aggregate: out[n] = relu(dinv[n]*(hws[n] + sum_{s in nbr(n)} hws[s]) + b)
__global__ void k_gather(const float* __restrict__ hws, const int* __restrict__ rowptr,
                         const int* __restrict__ col, const float* __restrict__ dinv,
                         const float* __restrict__ bias, float* __restrict__ out) {
    int gw = (blockIdx.x * blockDim.x + threadIdx.x) >> 5;
    if (gw >= NN) return;
    int lane = threadIdx.x & 31;
    const float4* base = (const float4*)hws;

    float4 acc = base[gw * 32 + lane];  // self-loop term (hws already scaled by dinv[src])
    float4 acc2 = make_float4(0.f, 0.f, 0.f, 0.f);

    int p = rowptr[gw];
    int p1 = rowptr[gw + 1];
    for (; p + 1 < p1; p += 2) {
        int s0 = col[p];
        int s1 = col[p + 1];
        float4 v0 = base[s0 * 32 + lane];
        float4 v1 = base[s1 * 32 + lane];
        acc.x += v0.x; acc.y += v0.y; acc.z += v0.z; acc.w += v0.w;
        acc2.x += v1.x; acc2.y += v1.y; acc2.z += v1.z; acc2.w += v1.w;
    }
    if (p < p1) {
        float4 v = base[col[p] * 32 + lane];
        acc.x += v.x; acc.y += v.y; acc.z += v.z; acc.w += v.w;
    }
    acc.x += acc2.x; acc.y += acc2.y; acc.z += acc2.z; acc.w += acc2.w;

    float dn = dinv[gw];
    float4 b = ((const float4*)bias)[lane];
    float4 o;
    o.x = fmaxf(fmaf(dn, acc.x, b.x), 0.f);
    o.y = fmaxf(fmaf(dn, acc.y, b.y), 0.f);
    o.z = fmaxf(fmaf(dn, acc.z, b.z), 0.f);
    o.w = fmaxf(fmaf(dn, acc.w, b.w), 0.f);
    ((float4*)out)[gw * 32 + lane] = o;
}

// ---------------- host launcher ----------------
extern "C" void kernel_launch(void* const* d_in, const int* in_sizes, int n_in,
                              void* d_out, int out_size) {
    const float* x      = (const float*)d_in[0];
    const int*   ei     = (const int*)d_in[1];
    const float* enc_w1 = (const float*)d_in[2];
    const float* enc_b1 = (const float*)d_in[3];
    const float* enc_w2 = (const float*)d_in[4];
    const float* enc_b2 = (const float*)d_in[5];
    const float* w_c1   = (const float*)d_in[6];
    const float* b_c1   = (const float*)d_in[7];
    const float* w_c2   = (const float*)d_in[8];
    const float* b_c2   = (const float*)d_in[9];
    const float* w_c3   = (const float*)d_in[10];
    const float* b_c3   = (const float*)d_in[11];
    const float* dec_w1 = (const float*)d_in[12];
    const float* dec_b1 = (const float*)d_in[13];
    const float* dec_w2 = (const float*)d_in[14];
    const float* dec_b2 = (const float*)d_in[15];
    float* out = (float*)d_out;

    float *buf0, *buf1, *buf2, *dinv;
    int *deg, *incl, *rowptr, *cursor, *col, *bsum, *btop;
    cudaGetSymbolAddress((void**)&buf0,   g_buf0);
    cudaGetSymbolAddress((void**)&buf1,   g_buf1);
    cudaGetSymbolAddress((void**)&buf2,   g_buf2);
    cudaGetSymbolAddress((void**)&dinv,   g_dinv);
    cudaGetSymbolAddress((void**)&deg,    g_deg);
    cudaGetSymbolAddress((void**)&incl,   g_incl);
    cudaGetSymbolAddress((void**)&rowptr, g_rowptr);
    cudaGetSymbolAddress((void**)&cursor, g_cursor);
    cudaGetSymbolAddress((void**)&col,    g_col);
    cudaGetSymbolAddress((void**)&bsum,   g_bsum);
    cudaGetSymbolAddress((void**)&btop,   g_btop);

    const int NB_N   = (NN + 255) / 256;
    const int NB_E   = (EE + 255) / 256;
    const int NB_SC  = (NN + 1023) / 1024;        // 49
    const int GB     = (NN + 63) / 64;            // 782 GEMM blocks
    const int NB_GAT = (NN * 32 + 255) / 256;     // one warp per node

    // --- graph preprocessing: degree -> dinv, CSR build ---
    k_init_deg<<<NB_N, 256>>>(deg);
    k_count<<<NB_E, 256>>>(ei, deg);
    k_scan_block<<<NB_SC, 1024>>>(deg, incl, bsum);
    k_scan_tops<<<1, 64>>>(bsum, btop, NB_SC);
    k_finalize<<<NB_N, 256>>>(deg, incl, btop, rowptr, cursor, dinv);
    k_fill<<<NB_E, 256>>>(ei, cursor, col);

    // --- encoder MLP ---
    k_gemm<FF, HH, M_RELU><<<GB, 256>>>(x,    enc_w1, enc_b1, nullptr, buf0);
    k_gemm<HH, HH, M_BIAS><<<GB, 256>>>(buf0, enc_w2, enc_b2, nullptr, buf1);

    // --- GCN conv 1 ---
    k_gemm<HH, HH, M_DINV><<<GB, 256>>>(buf1, w_c1, nullptr, dinv, buf2);
    k_gather<<<NB_GAT, 256>>>(buf2, rowptr, col, dinv, b_c1, buf0);

    // --- GCN conv 2 ---
    k_gemm<HH, HH, M_DINV><<<GB, 256>>>(buf0, w_c2, nullptr, dinv, buf1);
    k_gather<<<NB_GAT, 256>>>(buf1, rowptr, col, dinv, b_c2, buf2);

    // --- GCN conv 3 ---
    k_gemm<HH, HH, M_DINV><<<GB, 256>>>(buf2, w_c3, nullptr, dinv, buf0);
    k_gather<<<NB_GAT, 256>>>(buf0, rowptr, col, dinv, b_c3, buf1);

    // --- decoder MLP + sigmoid ---
    k_gemm<HH, HH, M_RELU><<<GB, 256>>>(buf1, dec_w1, dec_b1, nullptr, buf2);
    k_gemm<HH, FF, M_SIG><<<GB, 128>>>(buf2, dec_w2, dec_b2, nullptr, out);
}

// round 3
// speedup vs baseline: 2.1304x; 2.1304x over previous
#include <cuda_runtime.h>
#include <math.h>
#include <stdint.h>

#define NN 50000
#define EE 800000
#define FF 64
#define HH 128

#define M_RELU 0
#define M_BIAS 1
#define M_DINV 2
#define M_SIG  3

// ---------------- scratch (no allocations allowed) ----------------
__device__ float g_buf0[NN * HH];
__device__ float g_buf1[NN * HH];
__device__ float g_buf2[NN * HH];
__device__ float g_wt[98304];       // transposed weights
__device__ float g_dinv[NN];
__device__ int   g_deg[NN];
__device__ int   g_incl[NN];
__device__ int   g_rowptr[NN + 1];
__device__ int   g_cursor[NN];
__device__ int   g_col[EE];
__device__ int   g_bsum[64];
__device__ int   g_btop[64];

// ---------------- graph preprocessing ----------------
__global__ void k_init_deg(int* deg) {
    int i = blockIdx.x * blockDim.x + threadIdx.x;
    if (i < NN) deg[i] = 0;
}

__global__ void k_count(const int* __restrict__ ei, int* deg) {
    int e = blockIdx.x * blockDim.x + threadIdx.x;
    if (e < EE) atomicAdd(&deg[ei[EE + e]], 1);
}

__global__ void k_scan_block(const int* __restrict__ deg, int* incl, int* bsum) {
    __shared__ int s[1024];
    int i = blockIdx.x * 1024 + threadIdx.x;
    s[threadIdx.x] = (i < NN) ? deg[i] : 0;
    __syncthreads();
    for (int off = 1; off < 1024; off <<= 1) {
        int t = (threadIdx.x >= off) ? s[threadIdx.x - off] : 0;
        __syncthreads();
        s[threadIdx.x] += t;
        __syncthreads();
    }
    if (i < NN) incl[i] = s[threadIdx.x];
    if (threadIdx.x == 1023) bsum[blockIdx.x] = s[1023];
}

__global__ void k_scan_tops(const int* __restrict__ bsum, int* btop, int nb) {
    __shared__ int s[64];
    int t = threadIdx.x;
    s[t] = (t < nb) ? bsum[t] : 0;
    __syncthreads();
    for (int off = 1; off < 64; off <<= 1) {
        int v = (t >= off) ? s[t - off] : 0;
        __syncthreads();
        s[t] += v;
        __syncthreads();
    }
    btop[t] = s[t];
}

__global__ void k_finalize(const int* __restrict__ deg, const int* __restrict__ incl,
                           const int* __restrict__ btop,
                           int* rowptr, int* cursor, float* dinv) {
    int i = blockIdx.x * blockDim.x + threadIdx.x;
    if (i >= NN) return;
    int blk = i >> 10;
    int off = blk ? btop[blk - 1] : 0;
    int inc = incl[i] + off;
    int exc = inc - deg[i];
    rowptr[i] = exc;
    cursor[i] = exc;
    if (i == NN - 1) rowptr[NN] = inc;
    dinv[i] = rsqrtf((float)deg[i] + 1.0f);  // +1 for self-loop
}

__global__ void k_fill(const int* __restrict__ ei, int* cursor, int* col) {
    int e = blockIdx.x * blockDim.x + threadIdx.x;
    if (e >= EE) return;
    int s = ei[e];
    int d = ei[EE + e];
    int pos = atomicAdd(&cursor[d], 1);
    col[pos] = s;
}

// ---------------- weight transpose: W[K,N] -> WT[N,K], all 7 matrices ----------------
__global__ void k_transpose_all(const float* w0, const float* w1, const float* w2,
                                const float* w3, const float* w4, const float* w5,
                                const float* w6, float* wt) {
    __shared__ float tile[32][33];
    int b = blockIdx.x;
    int m, local;
    if (b < 8)       { m = 0; local = b; }
    else if (b < 88) { m = 1 + (b - 8) / 16; local = (b - 8) % 16; }
    else             { m = 6; local = b - 88; }
    const float* srcs[7] = {w0, w1, w2, w3, w4, w5, w6};
    const int Rs[7]   = {64, 128, 128, 128, 128, 128, 128};
    const int Cs[7]   = {128, 128, 128, 128, 128, 128, 64};
    const int offs[7] = {0, 8192, 24576, 40960, 57344, 73728, 90112};
    const float* src = srcs[m];
    float* dst = wt + offs[m];
    int R = Rs[m], C = Cs[m];
    int ct = C / 32;
    int tr = local / ct, tc = local % ct;
    int x = threadIdx.x % 32;
    int y0 = threadIdx.x / 32;
    for (int y = y0; y < 32; y += 8)
        tile[y][x] = src[(tr * 32 + y) * C + tc * 32 + x];
    __syncthreads();
    for (int y = y0; y < 32; y += 8)
        dst[(tc * 32 + y) * R + tr * 32 + x] = tile[x][y];
}

// ---------------- tf32 helpers ----------------
__device__ __forceinline__ float to_tf32(float x) {
    uint32_t o;
    asm("cvt.rna.tf32.f32 %0, %1;" : "=r"(o) : "f"(x));
    return __uint_as_float(o);
}

__device__ __forceinline__ void mma_m16n8k8(float* d, const float* a, float b0, float b1) {
    asm volatile(
        "mma.sync.aligned.m16n8k8.row.col.f32.tf32.tf32.f32 "
        "{%0,%1,%2,%3}, {%4,%5,%6,%7}, {%8,%9}, {%0,%1,%2,%3};"
        : "+f"(d[0]), "+f"(d[1]), "+f"(d[2]), "+f"(d[3])
        : "r"(__float_as_uint(a[0])), "r"(__float_as_uint(a[1])),
          "r"(__float_as_uint(a[2])), "r"(__float_as_uint(a[3])),
          "r"(__float_as_uint(b0)), "r"(__float_as_uint(b1)));
}

// ---------------- warp-MMA tf32 GEMM: C[NN,NC] = A[NN,K] @ WT[NC,K]^T ----------------
// 256 threads = 8 warps (4 in M x 2 in N). Block tile 128 x NC, BK = 32.
// Warp tile 32 x (NC/2): m16n8k8 grid of 2 x (NC/16).
template <int K, int NC, int MODE>
__global__ void __launch_bounds__(256)
k_wmma(const float* __restrict__ A, const float* __restrict__ WT,
       const float* __restrict__ bias, const float* __restrict__ dinv,
       float* __restrict__ C) {
    constexpr int BM = 128, BK = 32, PAD = 36;   // padded row stride (floats)
    constexpr int WNT = NC / 16;                 // n-tiles per warp (8 or 4)

    __shared__ float As[BM * PAD];
    __shared__ float Bs[NC * PAD];

    const int tid = threadIdx.x;
    const int lane = tid & 31;
    const int wid = tid >> 5;
    const int warp_m = (wid & 3) * 32;           // 4 warps cover 128 M-rows
    const int warp_n = (wid >> 2) * (NC / 2);    // 2 warps cover NC cols
    const int gid = lane >> 2;                   // group id (row within 8)
    const int tig = lane & 3;                    // thread in group
    const int row0 = blockIdx.x * BM;

    float acc[2][WNT][4];
#pragma unroll
    for (int mt = 0; mt < 2; mt++)
#pragma unroll
        for (int nt = 0; nt < WNT; nt++)
#pragma unroll
            for (int r = 0; r < 4; r++) acc[mt][nt][r] = 0.0f;

    for (int kk = 0; kk < K; kk += BK) {
        // stage A [BM, BK] (tf32-rounded), zero-fill OOB rows
#pragma unroll
        for (int i = tid; i < BM * (BK / 4); i += 256) {
            int r = i / (BK / 4), c4 = i % (BK / 4);
            float4 v = make_float4(0.f, 0.f, 0.f, 0.f);
            if (row0 + r < NN) v = *(const float4*)&A[(size_t)(row0 + r) * K + kk + c4 * 4];
            v.x = to_tf32(v.x); v.y = to_tf32(v.y); v.z = to_tf32(v.z); v.w = to_tf32(v.w);
            *(float4*)&As[r * PAD + c4 * 4] = v;
        }
        // stage B = WT [NC, BK] (tf32-rounded)
#pragma unroll
        for (int i = tid; i < NC * (BK / 4); i += 256) {
            int n = i / (BK / 4), c4 = i % (BK / 4);
            float4 v = *(const float4*)&WT[(size_t)n * K + kk + c4 * 4];
            v.x = to_tf32(v.x); v.y = to_tf32(v.y); v.z = to_tf32(v.z); v.w = to_tf32(v.w);
            *(float4*)&Bs[n * PAD + c4 * 4] = v;
        }
        __syncthreads();

#pragma unroll
        for (int ks = 0; ks < BK; ks += 8) {
            float a[2][4];
#pragma unroll
            for (int mt = 0; mt < 2; mt++) {
                int r = warp_m + mt * 16 + gid;
                a[mt][0] = As[r * PAD + ks + tig];
                a[mt][1] = As[(r + 8) * PAD + ks + tig];
                a[mt][2] = As[r * PAD + ks + tig + 4];
                a[mt][3] = As[(r + 8) * PAD + ks + tig + 4];
            }
#pragma unroll
            for (int nt = 0; nt < WNT; nt++) {
                int c = warp_n + nt * 8 + gid;
                float b0 = Bs[c * PAD + ks + tig];
                float b1 = Bs[c * PAD + ks + tig + 4];
#pragma unroll
                for (int mt = 0; mt < 2; mt++) mma_m16n8k8(acc[mt][nt], a[mt], b0, b1);
            }
        }
        __syncthreads();
    }

    // epilogue: reg r in {0,1}: row = base, col = tig*2 + r; r in {2,3}: row = base+8
#pragma unroll
    for (int mt = 0; mt < 2; mt++) {
#pragma unroll
        for (int half = 0; half < 2; half++) {
            int gr = row0 + warp_m + mt * 16 + gid + half * 8;
            if (gr >= NN) continue;
            float dn = (MODE == M_DINV) ? dinv[gr] : 0.0f;
#pragma unroll
            for (int nt = 0; nt < WNT; nt++) {
                int gc = warp_n + nt * 8 + tig * 2;
                float v0 = acc[mt][nt][half * 2 + 0];
                float v1 = acc[mt][nt][half * 2 + 1];
                if (MODE == M_DINV) {
                    v0 *= dn; v1 *= dn;
                } else {
                    float2 bb = *(const float2*)&bias[gc];
                    v0 += bb.x; v1 += bb.y;
                    if (MODE == M_RELU) { v0 = fmaxf(v0, 0.f); v1 = fmaxf(v1, 0.f); }
                    else if (MODE == M_SIG) {
                        v0 = 1.0f / (1.0f + expf(-v0));
                        v1 = 1.0f / (1.0f + expf(-v1));
                    }
                }
                *(float2*)&C[(size_t)gr * NC + gc] = make_float2(v0, v1);
            }
        }
    }
}

// ---------------- CSR gather-aggregate ----------------
__global__ void k_gather(const float* __restrict__ hws, const int* __restrict__ rowptr,
                         const int* __restrict__ col, const float* __restrict__ dinv,
                         const float* __restrict__ bias, float* __restrict__ out) {
    int gw = (blockIdx.x * blockDim.x + threadIdx.x) >> 5;
    if (gw >= NN) return;
    int lane = threadIdx.x & 31;
    const float4* base = (const float4*)hws;

    float4 acc = base[gw * 32 + lane];  // self-loop term
    float4 acc2 = make_float4(0.f, 0.f, 0.f, 0.f);

    int p = rowptr[gw];
    int p1 = rowptr[gw + 1];
    for (; p + 1 < p1; p += 2) {
        int s0 = col[p];
        int s1 = col[p + 1];
        float4 v0 = base[s0 * 32 + lane];
        float4 v1 = base[s1 * 32 + lane];
        acc.x += v0.x; acc.y += v0.y; acc.z += v0.z; acc.w += v0.w;
        acc2.x += v1.x; acc2.y += v1.y; acc2.z += v1.z; acc2.w += v1.w;
    }
    if (p < p1) {
        float4 v = base[col[p] * 32 + lane];
        acc.x += v.x; acc.y += v.y; acc.z += v.z; acc.w += v.w;
    }
    acc.x += acc2.x; acc.y += acc2.y; acc.z += acc2.z; acc.w += acc2.w;

    float dn = dinv[gw];
    float4 b = ((const float4*)bias)[lane];
    float4 o;
    o.x = fmaxf(fmaf(dn, acc.x, b.x), 0.f);
    o.y = fmaxf(fmaf(dn, acc.y, b.y), 0.f);
    o.z = fmaxf(fmaf(dn, acc.z, b.z), 0.f);
    o.w = fmaxf(fmaf(dn, acc.w, b.w), 0.f);
    ((float4*)out)[gw * 32 + lane] = o;
}

// ---------------- host launcher ----------------
extern "C" void kernel_launch(void* const* d_in, const int* in_sizes, int n_in,
                              void* d_out, int out_size) {
    const float* x      = (const float*)d_in[0];
    const int*   ei     = (const int*)d_in[1];
    const float* enc_w1 = (const float*)d_in[2];
    const float* enc_b1 = (const float*)d_in[3];
    const float* enc_w2 = (const float*)d_in[4];
    const float* enc_b2 = (const float*)d_in[5];
    const float* w_c1   = (const float*)d_in[6];
    const float* b_c1   = (const float*)d_in[7];
    const float* w_c2   = (const float*)d_in[8];
    const float* b_c2   = (const float*)d_in[9];
    const float* w_c3   = (const float*)d_in[10];
    const float* b_c3   = (const float*)d_in[11];
    const float* dec_w1 = (const float*)d_in[12];
    const float* dec_b1 = (const float*)d_in[13];
    const float* dec_w2 = (const float*)d_in[14];
    const float* dec_b2 = (const float*)d_in[15];
    float* out = (float*)d_out;

    float *buf0, *buf1, *buf2, *dinv, *wt;
    int *deg, *incl, *rowptr, *cursor, *col, *bsum, *btop;
    cudaGetSymbolAddress((void**)&buf0,   g_buf0);
    cudaGetSymbolAddress((void**)&buf1,   g_buf1);
    cudaGetSymbolAddress((void**)&buf2,   g_buf2);
    cudaGetSymbolAddress((void**)&wt,     g_wt);
    cudaGetSymbolAddress((void**)&dinv,   g_dinv);
    cudaGetSymbolAddress((void**)&deg,    g_deg);
    cudaGetSymbolAddress((void**)&incl,   g_incl);
    cudaGetSymbolAddress((void**)&rowptr, g_rowptr);
    cudaGetSymbolAddress((void**)&cursor, g_cursor);
    cudaGetSymbolAddress((void**)&col,    g_col);
    cudaGetSymbolAddress((void**)&bsum,   g_bsum);
    cudaGetSymbolAddress((void**)&btop,   g_btop);

    const int NB_N   = (NN + 255) / 256;
    const int NB_E   = (EE + 255) / 256;
    const int NB_SC  = (NN + 1023) / 1024;
    const int GB     = (NN + 127) / 128;          // 391 MMA blocks
    const int NB_GAT = (NN * 32 + 255) / 256;

    // --- graph preprocessing ---
    k_init_deg<<<NB_N, 256>>>(deg);
    k_count<<<NB_E, 256>>>(ei, deg);
    k_scan_block<<<NB_SC, 1024>>>(deg, incl, bsum);
    k_scan_tops<<<1, 64>>>(bsum, btop, NB_SC);
    k_finalize<<<NB_N, 256>>>(deg, incl, btop, rowptr, cursor, dinv);
    k_fill<<<NB_E, 256>>>(ei, cursor, col);

    // --- transpose all weights ---
    k_transpose_all<<<96, 256>>>(enc_w1, enc_w2, w_c1, w_c2, w_c3, dec_w1, dec_w2, wt);

    const float* wt_enc1 = wt + 0;
    const float* wt_enc2 = wt + 8192;
    const float* wt_c1   = wt + 24576;
    const float* wt_c2   = wt + 40960;
    const float* wt_c3   = wt + 57344;
    const float* wt_dec1 = wt + 73728;
    const float* wt_dec2 = wt + 90112;

    // --- encoder MLP ---
    k_wmma<64, 128, M_RELU><<<GB, 256>>>(x,    wt_enc1, enc_b1, nullptr, buf0);
    k_wmma<128, 128, M_BIAS><<<GB, 256>>>(buf0, wt_enc2, enc_b2, nullptr, buf1);

    // --- GCN conv 1 ---
    k_wmma<128, 128, M_DINV><<<GB, 256>>>(buf1, wt_c1, nullptr, dinv, buf2);
    k_gather<<<NB_GAT, 256>>>(buf2, rowptr, col, dinv, b_c1, buf0);

    // --- GCN conv 2 ---
    k_wmma<128, 128, M_DINV><<<GB, 256>>>(buf0, wt_c2, nullptr, dinv, buf1);
    k_gather<<<NB_GAT, 256>>>(buf1, rowptr, col, dinv, b_c2, buf2);

    // --- GCN conv 3 ---
    k_wmma<128, 128, M_DINV><<<GB, 256>>>(buf2, wt_c3, nullptr, dinv, buf0);
    k_gather<<<NB_GAT, 256>>>(buf0, rowptr, col, dinv, b_c3, buf1);

    // --- decoder MLP + sigmoid ---
    k_wmma<128, 128, M_RELU><<<GB, 256>>>(buf1, wt_dec1, dec_b1, nullptr, buf2);
    k_wmma<128, 64, M_SIG><<<GB, 256>>>(buf2, wt_dec2, dec_b2, nullptr, out);
}

// round 4
// speedup vs baseline: 2.3822x; 1.1182x over previous
#include <cuda_runtime.h>
#include <cuda_fp16.h>
#include <math.h>
#include <stdint.h>

#define NN 50000
#define EE 800000
#define FF 64
#define HH 128

#define M_RELU 0
#define M_BIAS 1
#define M_DINV 2
#define M_SIG  3

// ---------------- scratch (no allocations allowed) ----------------
__device__ float  g_buf0[NN * HH];
__device__ float  g_buf1[NN * HH];
__device__ float  g_buf2[NN * HH];
__device__ __half g_hbuf[NN * HH];   // fp16 message rows (hws)
__device__ float  g_wt[98304];       // transposed weights
__device__ float  g_dinv[NN];
__device__ int    g_deg[NN];
__device__ int    g_incl[NN];
__device__ int    g_rowptr[NN + 1];
__device__ int    g_cursor[NN];
__device__ int    g_col[EE];
__device__ int    g_bsum[64];

// ---------------- graph preprocessing ----------------
__global__ void k_init_deg(int* deg) {
    int i = blockIdx.x * blockDim.x + threadIdx.x;
    if (i < NN) deg[i] = 0;
}

__global__ void k_count(const int* __restrict__ ei, int* deg) {
    int e = blockIdx.x * blockDim.x + threadIdx.x;
    if (e < EE) atomicAdd(&deg[ei[EE + e]], 1);
}

__global__ void k_scan_block(const int* __restrict__ deg, int* incl, int* bsum) {
    __shared__ int s[1024];
    int i = blockIdx.x * 1024 + threadIdx.x;
    s[threadIdx.x] = (i < NN) ? deg[i] : 0;
    __syncthreads();
    for (int off = 1; off < 1024; off <<= 1) {
        int t = (threadIdx.x >= off) ? s[threadIdx.x - off] : 0;
        __syncthreads();
        s[threadIdx.x] += t;
        __syncthreads();
    }
    if (i < NN) incl[i] = s[threadIdx.x];
    if (threadIdx.x == 1023) bsum[blockIdx.x] = s[1023];
}

// finalize with inline block-sum prefix (replaces k_scan_tops)
__global__ void k_finalize(const int* __restrict__ deg, const int* __restrict__ incl,
                           const int* __restrict__ bsum,
                           int* rowptr, int* cursor, float* dinv) {
    __shared__ int sb[64];
    if (threadIdx.x < 49) sb[threadIdx.x] = bsum[threadIdx.x];
    __syncthreads();
    int i = blockIdx.x * blockDim.x + threadIdx.x;
    if (i >= NN) return;
    int blk = i >> 10;
    int off = 0;
    for (int j = 0; j < blk; j++) off += sb[j];
    int inc = incl[i] + off;
    int exc = inc - deg[i];
    rowptr[i] = exc;
    cursor[i] = exc;
    if (i == NN - 1) rowptr[NN] = inc;
    dinv[i] = rsqrtf((float)deg[i] + 1.0f);  // +1 for self-loop
}

__global__ void k_fill(const int* __restrict__ ei, int* cursor, int* col) {
    int e = blockIdx.x * blockDim.x + threadIdx.x;
    if (e >= EE) return;
    int s = ei[e];
    int d = ei[EE + e];
    int pos = atomicAdd(&cursor[d], 1);
    col[pos] = s;
}

// ---------------- weight transpose: W[K,N] -> WT[N,K], all 7 matrices ----------------
__global__ void k_transpose_all(const float* w0, const float* w1, const float* w2,
                                const float* w3, const float* w4, const float* w5,
                                const float* w6, float* wt) {
    __shared__ float tile[32][33];
    int b = blockIdx.x;
    int m, local;
    if (b < 8)       { m = 0; local = b; }
    else if (b < 88) { m = 1 + (b - 8) / 16; local = (b - 8) % 16; }
    else             { m = 6; local = b - 88; }
    const float* srcs[7] = {w0, w1, w2, w3, w4, w5, w6};
    const int Rs[7]   = {64, 128, 128, 128, 128, 128, 128};
    const int Cs[7]   = {128, 128, 128, 128, 128, 128, 64};
    const int offs[7] = {0, 8192, 24576, 40960, 57344, 73728, 90112};
    const float* src = srcs[m];
    float* dst = wt + offs[m];
    int R = Rs[m], C = Cs[m];
    int ct = C / 32;
    int tr = local / ct, tc = local % ct;
    int x = threadIdx.x % 32;
    int y0 = threadIdx.x / 32;
    for (int y = y0; y < 32; y += 8)
        tile[y][x] = src[(tr * 32 + y) * C + tc * 32 + x];
    __syncthreads();
    for (int y = y0; y < 32; y += 8)
        dst[(tc * 32 + y) * R + tr * 32 + x] = tile[x][y];
}

// ---------------- tf32 helpers ----------------
__device__ __forceinline__ float to_tf32(float x) {
    uint32_t o;
    asm("cvt.rna.tf32.f32 %0, %1;" : "=r"(o) : "f"(x));
    return __uint_as_float(o);
}

__device__ __forceinline__ void mma_m16n8k8(float* d, const float* a, float b0, float b1) {
    asm volatile(
        "mma.sync.aligned.m16n8k8.row.col.f32.tf32.tf32.f32 "
        "{%0,%1,%2,%3}, {%4,%5,%6,%7}, {%8,%9}, {%0,%1,%2,%3};"
        : "+f"(d[0]), "+f"(d[1]), "+f"(d[2]), "+f"(d[3])
        : "r"(__float_as_uint(a[0])), "r"(__float_as_uint(a[1])),
          "r"(__float_as_uint(a[2])), "r"(__float_as_uint(a[3])),
          "r"(__float_as_uint(b0)), "r"(__float_as_uint(b1)));
}

// ---------------- warp-MMA tf32 GEMM: C[NN,NC] = A[NN,K] @ WT[NC,K]^T ----------------
// 256 threads = 8 warps (4 in M x 2 in N). Block tile 128 x NC, BK = 32.
// HOUT: write __half2-packed output (used for conv message rows).
template <int K, int NC, int MODE, bool HOUT>
__global__ void __launch_bounds__(256)
k_wmma(const float* __restrict__ A, const float* __restrict__ WT,
       const float* __restrict__ bias, const float* __restrict__ dinv,
       void* __restrict__ Cv) {
    constexpr int BM = 128, BK = 32, PAD = 36;
    constexpr int WNT = NC / 16;

    __shared__ float As[BM * PAD];
    __shared__ float Bs[NC * PAD];

    const int tid = threadIdx.x;
    const int lane = tid & 31;
    const int wid = tid >> 5;
    const int warp_m = (wid & 3) * 32;
    const int warp_n = (wid >> 2) * (NC / 2);
    const int gid = lane >> 2;
    const int tig = lane & 3;
    const int row0 = blockIdx.x * BM;

    float acc[2][WNT][4];
#pragma unroll
    for (int mt = 0; mt < 2; mt++)
#pragma unroll
        for (int nt = 0; nt < WNT; nt++)
#pragma unroll
            for (int r = 0; r < 4; r++) acc[mt][nt][r] = 0.0f;

    for (int kk = 0; kk < K; kk += BK) {
#pragma unroll
        for (int i = tid; i < BM * (BK / 4); i += 256) {
            int r = i / (BK / 4), c4 = i % (BK / 4);
            float4 v = make_float4(0.f, 0.f, 0.f, 0.f);
            if (row0 + r < NN) v = *(const float4*)&A[(size_t)(row0 + r) * K + kk + c4 * 4];
            v.x = to_tf32(v.x); v.y = to_tf32(v.y); v.z = to_tf32(v.z); v.w = to_tf32(v.w);
            *(float4*)&As[r * PAD + c4 * 4] = v;
        }
#pragma unroll
        for (int i = tid; i < NC * (BK / 4); i += 256) {
            int n = i / (BK / 4), c4 = i % (BK / 4);
            float4 v = *(const float4*)&WT[(size_t)n * K + kk + c4 * 4];
            v.x = to_tf32(v.x); v.y = to_tf32(v.y); v.z = to_tf32(v.z); v.w = to_tf32(v.w);
            *(float4*)&Bs[n * PAD + c4 * 4] = v;
        }
        __syncthreads();

#pragma unroll
        for (int ks = 0; ks < BK; ks += 8) {
            float a[2][4];
#pragma unroll
            for (int mt = 0; mt < 2; mt++) {
                int r = warp_m + mt * 16 + gid;
                a[mt][0] = As[r * PAD + ks + tig];
                a[mt][1] = As[(r + 8) * PAD + ks + tig];
                a[mt][2] = As[r * PAD + ks + tig + 4];
                a[mt][3] = As[(r + 8) * PAD + ks + tig + 4];
            }
#pragma unroll
            for (int nt = 0; nt < WNT; nt++) {
                int c = warp_n + nt * 8 + gid;
                float b0 = Bs[c * PAD + ks + tig];
                float b1 = Bs[c * PAD + ks + tig + 4];
#pragma unroll
                for (int mt = 0; mt < 2; mt++) mma_m16n8k8(acc[mt][nt], a[mt], b0, b1);
            }
        }
        __syncthreads();
    }

    float* Cf = (float*)Cv;
    __half2* Ch = (__half2*)Cv;

#pragma unroll
    for (int mt = 0; mt < 2; mt++) {
#pragma unroll
        for (int half = 0; half < 2; half++) {
            int gr = row0 + warp_m + mt * 16 + gid + half * 8;
            if (gr >= NN) continue;
            float dn = (MODE == M_DINV) ? dinv[gr] : 0.0f;
#pragma unroll
            for (int nt = 0; nt < WNT; nt++) {
                int gc = warp_n + nt * 8 + tig * 2;
                float v0 = acc[mt][nt][half * 2 + 0];
                float v1 = acc[mt][nt][half * 2 + 1];
                if (MODE == M_DINV) {
                    v0 *= dn; v1 *= dn;
                } else {
                    float2 bb = *(const float2*)&bias[gc];
                    v0 += bb.x; v1 += bb.y;
                    if (MODE == M_RELU) { v0 = fmaxf(v0, 0.f); v1 = fmaxf(v1, 0.f); }
                    else if (MODE == M_SIG) {
                        v0 = 1.0f / (1.0f + expf(-v0));
                        v1 = 1.0f / (1.0f + expf(-v1));
                    }
                }
                if (HOUT) {
                    Ch[(size_t)gr * (NC / 2) + (gc >> 1)] = __floats2half2_rn(v0, v1);
                } else {
                    *(float2*)&Cf[(size_t)gr * NC + gc] = make_float2(v0, v1);
                }
            }
        }
    }
}

// ---------------- CSR gather-aggregate over fp16 message rows ----------------
// Row = 128 half = 64 half2 = 32 uint2. One warp per node; lane owns 4 channels.
__global__ void k_gather_h(const __half* __restrict__ hws, const int* __restrict__ rowptr,
                           const int* __restrict__ col, const float* __restrict__ dinv,
                           const float* __restrict__ bias, float* __restrict__ out) {
    int gw = (blockIdx.x * blockDim.x + threadIdx.x) >> 5;
    if (gw >= NN) return;
    int lane = threadIdx.x & 31;
    const uint2* base = (const uint2*)hws;   // 32 uint2 per row

    // self-loop term
    uint2 s = base[(size_t)gw * 32 + lane];
    float2 f0 = __half22float2(*(const __half2*)&s.x);
    float2 f1 = __half22float2(*(const __half2*)&s.y);
    float a0 = f0.x, a1 = f0.y, a2 = f1.x, a3 = f1.y;
    float c0 = 0.f, c1 = 0.f, c2 = 0.f, c3 = 0.f;

    int p = rowptr[gw];
    int p1 = rowptr[gw + 1];
    for (; p + 1 < p1; p += 2) {
        int s0 = col[p];
        int s1 = col[p + 1];
        uint2 v0 = base[(size_t)s0 * 32 + lane];
        uint2 v1 = base[(size_t)s1 * 32 + lane];
        float2 g0 = __half22float2(*(const __half2*)&v0.x);
        float2 g1 = __half22float2(*(const __half2*)&v0.y);
        float2 h0 = __half22float2(*(const __half2*)&v1.x);
        float2 h1 = __half22float2(*(const __half2*)&v1.y);
        a0 += g0.x; a1 += g0.y; a2 += g1.x; a3 += g1.y;
        c0 += h0.x; c1 += h0.y; c2 += h1.x; c3 += h1.y;
    }
    if (p < p1) {
        uint2 v = base[(size_t)col[p] * 32 + lane];
        float2 g0 = __half22float2(*(const __half2*)&v.x);
        float2 g1 = __half22float2(*(const __half2*)&v.y);
        a0 += g0.x; a1 += g0.y; a2 += g1.x; a3 += g1.y;
    }
    a0 += c0; a1 += c1; a2 += c2; a3 += c3;

    float dn = dinv[gw];
    float4 b = ((const float4*)bias)[lane];
    float4 o;
    o.x = fmaxf(fmaf(dn, a0, b.x), 0.f);
    o.y = fmaxf(fmaf(dn, a1, b.y), 0.f);
    o.z = fmaxf(fmaf(dn, a2, b.z), 0.f);
    o.w = fmaxf(fmaf(dn, a3, b.w), 0.f);
    ((float4*)out)[(size_t)gw * 32 + lane] = o;
}

// ---------------- host launcher ----------------
extern "C" void kernel_launch(void* const* d_in, const int* in_sizes, int n_in,
                              void* d_out, int out_size) {
    const float* x      = (const float*)d_in[0];
    const int*   ei     = (const int*)d_in[1];
    const float* enc_w1 = (const float*)d_in[2];
    const float* enc_b1 = (const float*)d_in[3];
    const float* enc_w2 = (const float*)d_in[4];
    const float* enc_b2 = (const float*)d_in[5];
    const float* w_c1   = (const float*)d_in[6];
    const float* b_c1   = (const float*)d_in[7];
    const float* w_c2   = (const float*)d_in[8];
    const float* b_c2   = (const float*)d_in[9];
    const float* w_c3   = (const float*)d_in[10];
    const float* b_c3   = (const float*)d_in[11];
    const float* dec_w1 = (const float*)d_in[12];
    const float* dec_b1 = (const float*)d_in[13];
    const float* dec_w2 = (const float*)d_in[14];
    const float* dec_b2 = (const float*)d_in[15];
    float* out = (float*)d_out;

    float *buf0, *buf1, *buf2, *dinv, *wt;
    __half* hbuf;
    int *deg, *incl, *rowptr, *cursor, *col, *bsum;
    cudaGetSymbolAddress((void**)&buf0,   g_buf0);
    cudaGetSymbolAddress((void**)&buf1,   g_buf1);
    cudaGetSymbolAddress((void**)&buf2,   g_buf2);
    cudaGetSymbolAddress((void**)&hbuf,   g_hbuf);
    cudaGetSymbolAddress((void**)&wt,     g_wt);
    cudaGetSymbolAddress((void**)&dinv,   g_dinv);
    cudaGetSymbolAddress((void**)&deg,    g_deg);
    cudaGetSymbolAddress((void**)&incl,   g_incl);
    cudaGetSymbolAddress((void**)&rowptr, g_rowptr);
    cudaGetSymbolAddress((void**)&cursor, g_cursor);
    cudaGetSymbolAddress((void**)&col,    g_col);
    cudaGetSymbolAddress((void**)&bsum,   g_bsum);

    const int NB_N   = (NN + 255) / 256;
    const int NB_E   = (EE + 255) / 256;
    const int NB_SC  = (NN + 1023) / 1024;
    const int GB     = (NN + 127) / 128;
    const int NB_GAT = (NN * 32 + 255) / 256;

    // --- graph preprocessing ---
    k_init_deg<<<NB_N, 256>>>(deg);
    k_count<<<NB_E, 256>>>(ei, deg);
    k_scan_block<<<NB_SC, 1024>>>(deg, incl, bsum);
    k_finalize<<<NB_N, 256>>>(deg, incl, bsum, rowptr, cursor, dinv);
    k_fill<<<NB_E, 256>>>(ei, cursor, col);

    // --- transpose all weights ---
    k_transpose_all<<<96, 256>>>(enc_w1, enc_w2, w_c1, w_c2, w_c3, dec_w1, dec_w2, wt);

    const float* wt_enc1 = wt + 0;
    const float* wt_enc2 = wt + 8192;
    const float* wt_c1   = wt + 24576;
    const float* wt_c2   = wt + 40960;
    const float* wt_c3   = wt + 57344;
    const float* wt_dec1 = wt + 73728;
    const float* wt_dec2 = wt + 90112;

    // --- encoder MLP ---
    k_wmma<64, 128, M_RELU, false><<<GB, 256>>>(x,    wt_enc1, enc_b1, nullptr, buf0);
    k_wmma<128, 128, M_BIAS, false><<<GB, 256>>>(buf0, wt_enc2, enc_b2, nullptr, buf1);

    // --- GCN conv 1 ---
    k_wmma<128, 128, M_DINV, true><<<GB, 256>>>(buf1, wt_c1, nullptr, dinv, hbuf);
    k_gather_h<<<NB_GAT, 256>>>(hbuf, rowptr, col, dinv, b_c1, buf0);

    // --- GCN conv 2 ---
    k_wmma<128, 128, M_DINV, true><<<GB, 256>>>(buf0, wt_c2, nullptr, dinv, hbuf);
    k_gather_h<<<NB_GAT, 256>>>(hbuf, rowptr, col, dinv, b_c2, buf1);

    // --- GCN conv 3 ---
    k_wmma<128, 128, M_DINV, true><<<GB, 256>>>(buf1, wt_c3, nullptr, dinv, hbuf);
    k_gather_h<<<NB_GAT, 256>>>(hbuf, rowptr, col, dinv, b_c3, buf2);

    // --- decoder MLP + sigmoid ---
    k_wmma<128, 128, M_RELU, false><<<GB, 256>>>(buf2, wt_dec1, dec_b1, nullptr, buf0);
    k_wmma<128, 64, M_SIG, false><<<GB, 256>>>(buf0, wt_dec2, dec_b2, nullptr, out);
}

// round 6
// speedup vs baseline: 3.0178x; 1.2668x over previous
#include <cuda_runtime.h>
#include <cuda_fp16.h>
#include <math.h>
#include <stdint.h>

#define NN 50000
#define EE 800000
#define FF 64
#define HH 128

#define M_RELU 0
#define M_BIAS 1
#define M_DINV 2
#define M_SIG  3

// ---------------- scratch (no allocations allowed) ----------------
__device__ __half g_hb0[NN * HH];
__device__ __half g_hb1[NN * HH];
__device__ __half g_hb2[NN * HH];
__device__ __half g_wth[98304];     // transposed fp16 weights
__device__ float  g_dinv[NN];
__device__ int    g_deg[NN];
__device__ int    g_incl[NN];
__device__ int    g_rowptr[NN + 1];
__device__ int    g_cursor[NN];
__device__ int    g_col[EE];
__device__ int    g_bsum[64];

// ---------------- graph preprocessing ----------------
__global__ void k_init_deg(int* deg) {
    int i = blockIdx.x * blockDim.x + threadIdx.x;
    if (i < NN) deg[i] = 0;
}

__global__ void k_count(const int* __restrict__ ei, int* deg) {
    int e = blockIdx.x * blockDim.x + threadIdx.x;
    if (e < EE) atomicAdd(&deg[ei[EE + e]], 1);
}

__global__ void k_scan_block(const int* __restrict__ deg, int* incl, int* bsum) {
    __shared__ int s[1024];
    int i = blockIdx.x * 1024 + threadIdx.x;
    s[threadIdx.x] = (i < NN) ? deg[i] : 0;
    __syncthreads();
    for (int off = 1; off < 1024; off <<= 1) {
        int t = (threadIdx.x >= off) ? s[threadIdx.x - off] : 0;
        __syncthreads();
        s[threadIdx.x] += t;
        __syncthreads();
    }
    if (i < NN) incl[i] = s[threadIdx.x];
    if (threadIdx.x == 1023) bsum[blockIdx.x] = s[1023];
}

__global__ void k_finalize(const int* __restrict__ deg, const int* __restrict__ incl,
                           const int* __restrict__ bsum,
                           int* rowptr, int* cursor, float* dinv) {
    __shared__ int sb[64];
    if (threadIdx.x < 49) sb[threadIdx.x] = bsum[threadIdx.x];
    __syncthreads();
    int i = blockIdx.x * blockDim.x + threadIdx.x;
    if (i >= NN) return;
    int blk = i >> 10;
    int off = 0;
    for (int j = 0; j < blk; j++) off += sb[j];
    int inc = incl[i] + off;
    int exc = inc - deg[i];
    rowptr[i] = exc;
    cursor[i] = exc;
    if (i == NN - 1) rowptr[NN] = inc;
    dinv[i] = rsqrtf((float)deg[i] + 1.0f);
}

__global__ void k_fill(const int* __restrict__ ei, int* cursor, int* col) {
    int e = blockIdx.x * blockDim.x + threadIdx.x;
    if (e >= EE) return;
    int s = ei[e];
    int d = ei[EE + e];
    int pos = atomicAdd(&cursor[d], 1);
    col[pos] = s;
}

// ---------------- weight transpose+convert: W[K,N] f32 -> WT[N,K] f16 ----------------
__global__ void k_transpose_all(const float* w0, const float* w1, const float* w2,
                                const float* w3, const float* w4, const float* w5,
                                const float* w6, __half* wt) {
    __shared__ float tile[32][33];
    int b = blockIdx.x;
    int m, local;
    if (b < 8)       { m = 0; local = b; }
    else if (b < 88) { m = 1 + (b - 8) / 16; local = (b - 8) % 16; }
    else             { m = 6; local = b - 88; }
    const float* srcs[7] = {w0, w1, w2, w3, w4, w5, w6};
    const int Rs[7]   = {64, 128, 128, 128, 128, 128, 128};
    const int Cs[7]   = {128, 128, 128, 128, 128, 128, 64};
    const int offs[7] = {0, 8192, 24576, 40960, 57344, 73728, 90112};
    const float* src = srcs[m];
    __half* dst = wt + offs[m];
    int R = Rs[m], C = Cs[m];
    int ct = C / 32;
    int tr = local / ct, tc = local % ct;
    int x = threadIdx.x % 32;
    int y0 = threadIdx.x / 32;
    for (int y = y0; y < 32; y += 8)
        tile[y][x] = src[(tr * 32 + y) * C + tc * 32 + x];
    __syncthreads();
    for (int y = y0; y < 32; y += 8)
        dst[(tc * 32 + y) * R + tr * 32 + x] = __float2half(tile[x][y]);
}

// ---------------- fp16 MMA helper ----------------
__device__ __forceinline__ void mma_f16(float* d, const uint32_t* a, uint32_t b0, uint32_t b1) {
    asm volatile(
        "mma.sync.aligned.m16n8k16.row.col.f32.f16.f16.f32 "
        "{%0,%1,%2,%3}, {%4,%5,%6,%7}, {%8,%9}, {%0,%1,%2,%3};"
        : "+f"(d[0]), "+f"(d[1]), "+f"(d[2]), "+f"(d[3])
        : "r"(a[0]), "r"(a[1]), "r"(a[2]), "r"(a[3]), "r"(b0), "r"(b1));
}

// ---------------- fp16 warp-MMA GEMM: C[NN,NC] = A[NN,K] @ WT[NC,K]^T ----------------
// 256 threads = 8 warps (4 in M x 2 in N). Block tile 128 x NC, BK = 64 (fp16 smem).
// AH: A is fp16; else fp32 (first layer reads x). HOUT: fp16 output, else fp32.
template <int K, int NC, int MODE, bool AH, bool HOUT>
__global__ void __launch_bounds__(256)
k_hmma(const void* __restrict__ Av, const __half* __restrict__ WT,
       const float* __restrict__ bias, const float* __restrict__ dinv,
       void* __restrict__ Cv) {
    constexpr int BM = 128, BK = 64, PADH = BK + 8;   // halves per smem row
    constexpr int WNT = NC / 16;

    __shared__ __half As[BM * PADH];
    __shared__ __half Bs[NC * PADH];

    const int tid = threadIdx.x;
    const int lane = tid & 31;
    const int wid = tid >> 5;
    const int warp_m = (wid & 3) * 32;
    const int warp_n = (wid >> 2) * (NC / 2);
    const int gid = lane >> 2;
    const int tig = lane & 3;
    const int row0 = blockIdx.x * BM;

    const __half* Ah = (const __half*)Av;
    const float*  Af = (const float*)Av;

    float acc[2][WNT][4];
#pragma unroll
    for (int mt = 0; mt < 2; mt++)
#pragma unroll
        for (int nt = 0; nt < WNT; nt++)
#pragma unroll
            for (int r = 0; r < 4; r++) acc[mt][nt][r] = 0.0f;

    for (int kk = 0; kk < K; kk += BK) {
        // stage A [BM, BK] in units of 8 halves
#pragma unroll
        for (int i = tid; i < BM * (BK / 8); i += 256) {
            int r = i / (BK / 8), c8 = i % (BK / 8);
            uint4 u = make_uint4(0, 0, 0, 0);
            if (row0 + r < NN) {
                if (AH) {
                    u = *(const uint4*)&Ah[(size_t)(row0 + r) * K + kk + c8 * 8];
                } else {
                    float4 f0 = *(const float4*)&Af[(size_t)(row0 + r) * K + kk + c8 * 8];
                    float4 f1 = *(const float4*)&Af[(size_t)(row0 + r) * K + kk + c8 * 8 + 4];
                    __half2 h0 = __floats2half2_rn(f0.x, f0.y);
                    __half2 h1 = __floats2half2_rn(f0.z, f0.w);
                    __half2 h2 = __floats2half2_rn(f1.x, f1.y);
                    __half2 h3 = __floats2half2_rn(f1.z, f1.w);
                    u.x = *(uint32_t*)&h0; u.y = *(uint32_t*)&h1;
                    u.z = *(uint32_t*)&h2; u.w = *(uint32_t*)&h3;
                }
            }
            *(uint4*)&As[r * PADH + c8 * 8] = u;
        }
        // stage B = WT [NC, BK]
#pragma unroll
        for (int i = tid; i < NC * (BK / 8); i += 256) {
            int n = i / (BK / 8), c8 = i % (BK / 8);
            *(uint4*)&Bs[n * PADH + c8 * 8] =
                *(const uint4*)&WT[(size_t)n * K + kk + c8 * 8];
        }
        __syncthreads();

#pragma unroll
        for (int ks = 0; ks < BK; ks += 16) {
            uint32_t a[2][4];
#pragma unroll
            for (int mt = 0; mt < 2; mt++) {
                int r = warp_m + mt * 16 + gid;
                a[mt][0] = *(const uint32_t*)&As[r * PADH + ks + 2 * tig];
                a[mt][1] = *(const uint32_t*)&As[(r + 8) * PADH + ks + 2 * tig];
                a[mt][2] = *(const uint32_t*)&As[r * PADH + ks + 2 * tig + 8];
                a[mt][3] = *(const uint32_t*)&As[(r + 8) * PADH + ks + 2 * tig + 8];
            }
#pragma unroll
            for (int nt = 0; nt < WNT; nt++) {
                int c = warp_n + nt * 8 + gid;
                uint32_t b0 = *(const uint32_t*)&Bs[c * PADH + ks + 2 * tig];
                uint32_t b1 = *(const uint32_t*)&Bs[c * PADH + ks + 2 * tig + 8];
#pragma unroll
                for (int mt = 0; mt < 2; mt++) mma_f16(acc[mt][nt], a[mt], b0, b1);
            }
        }
        __syncthreads();
    }

    float*   Cf = (float*)Cv;
    __half2* Ch = (__half2*)Cv;

#pragma unroll
    for (int mt = 0; mt < 2; mt++) {
#pragma unroll
        for (int half = 0; half < 2; half++) {
            int gr = row0 + warp_m + mt * 16 + gid + half * 8;
            if (gr >= NN) continue;
            float dn = (MODE == M_DINV) ? dinv[gr] : 0.0f;
#pragma unroll
            for (int nt = 0; nt < WNT; nt++) {
                int gc = warp_n + nt * 8 + tig * 2;
                float v0 = acc[mt][nt][half * 2 + 0];
                float v1 = acc[mt][nt][half * 2 + 1];
                if (MODE == M_DINV) {
                    v0 *= dn; v1 *= dn;
                } else {
                    float2 bb = *(const float2*)&bias[gc];
                    v0 += bb.x; v1 += bb.y;
                    if (MODE == M_RELU) { v0 = fmaxf(v0, 0.f); v1 = fmaxf(v1, 0.f); }
                    else if (MODE == M_SIG) {
                        v0 = 1.0f / (1.0f + expf(-v0));
                        v1 = 1.0f / (1.0f + expf(-v1));
                    }
                }
                if (HOUT) {
                    Ch[(size_t)gr * (NC / 2) + (gc >> 1)] = __floats2half2_rn(v0, v1);
                } else {
                    *(float2*)&Cf[(size_t)gr * NC + gc] = make_float2(v0, v1);
                }
            }
        }
    }
}

// ---------------- CSR gather-aggregate over fp16 rows, fp16 out ----------------
__global__ void k_gather_h(const __half* __restrict__ hws, const int* __restrict__ rowptr,
                           const int* __restrict__ col, const float* __restrict__ dinv,
                           const float* __restrict__ bias, __half* __restrict__ out) {
    int gw = (blockIdx.x * blockDim.x + threadIdx.x) >> 5;
    if (gw >= NN) return;
    int lane = threadIdx.x & 31;
    const uint2* base = (const uint2*)hws;   // 32 uint2 per 128-half row

    uint2 s = base[(size_t)gw * 32 + lane];  // self-loop
    float2 f0 = __half22float2(*(const __half2*)&s.x);
    float2 f1 = __half22float2(*(const __half2*)&s.y);
    float a0 = f0.x, a1 = f0.y, a2 = f1.x, a3 = f1.y;
    float c0 = 0.f, c1 = 0.f, c2 = 0.f, c3 = 0.f;

    int p = rowptr[gw];
    int p1 = rowptr[gw + 1];
    for (; p + 1 < p1; p += 2) {
        int s0 = col[p];
        int s1 = col[p + 1];
        uint2 v0 = base[(size_t)s0 * 32 + lane];
        uint2 v1 = base[(size_t)s1 * 32 + lane];
        float2 g0 = __half22float2(*(const __half2*)&v0.x);
        float2 g1 = __half22float2(*(const __half2*)&v0.y);
        float2 h0 = __half22float2(*(const __half2*)&v1.x);
        float2 h1 = __half22float2(*(const __half2*)&v1.y);
        a0 += g0.x; a1 += g0.y; a2 += g1.x; a3 += g1.y;
        c0 += h0.x; c1 += h0.y; c2 += h1.x; c3 += h1.y;
    }
    if (p < p1) {
        uint2 v = base[(size_t)col[p] * 32 + lane];
        float2 g0 = __half22float2(*(const __half2*)&v.x);
        float2 g1 = __half22float2(*(const __half2*)&v.y);
        a0 += g0.x; a1 += g0.y; a2 += g1.x; a3 += g1.y;
    }
    a0 += c0; a1 += c1; a2 += c2; a3 += c3;

    float dn = dinv[gw];
    float4 b = ((const float4*)bias)[lane];
    float o0 = fmaxf(fmaf(dn, a0, b.x), 0.f);
    float o1 = fmaxf(fmaf(dn, a1, b.y), 0.f);
    float o2 = fmaxf(fmaf(dn, a2, b.z), 0.f);
    float o3 = fmaxf(fmaf(dn, a3, b.w), 0.f);
    __half2 h0 = __floats2half2_rn(o0, o1);
    __half2 h1 = __floats2half2_rn(o2, o3);
    uint2 w;
    w.x = *(uint32_t*)&h0;
    w.y = *(uint32_t*)&h1;
    ((uint2*)out)[(size_t)gw * 32 + lane] = w;
}

// ---------------- host launcher ----------------
extern "C" void kernel_launch(void* const* d_in, const int* in_sizes, int n_in,
                              void* d_out, int out_size) {
    const float* x      = (const float*)d_in[0];
    const int*   ei     = (const int*)d_in[1];
    const float* enc_w1 = (const float*)d_in[2];
    const float* enc_b1 = (const float*)d_in[3];
    const float* enc_w2 = (const float*)d_in[4];
    const float* enc_b2 = (const float*)d_in[5];
    const float* w_c1   = (const float*)d_in[6];
    const float* b_c1   = (const float*)d_in[7];
    const float* w_c2   = (const float*)d_in[8];
    const float* b_c2   = (const float*)d_in[9];
    const float* w_c3   = (const float*)d_in[10];
    const float* b_c3   = (const float*)d_in[11];
    const float* dec_w1 = (const float*)d_in[12];
    const float* dec_b1 = (const float*)d_in[13];
    const float* dec_w2 = (const float*)d_in[14];
    const float* dec_b2 = (const float*)d_in[15];
    float* out = (float*)d_out;

    __half *hb0, *hb1, *hb2, *wth;
    float *dinv;
    int *deg, *incl, *rowptr, *cursor, *col, *bsum;
    cudaGetSymbolAddress((void**)&hb0,    g_hb0);
    cudaGetSymbolAddress((void**)&hb1,    g_hb1);
    cudaGetSymbolAddress((void**)&hb2,    g_hb2);
    cudaGetSymbolAddress((void**)&wth,    g_wth);
    cudaGetSymbolAddress((void**)&dinv,   g_dinv);
    cudaGetSymbolAddress((void**)&deg,    g_deg);
    cudaGetSymbolAddress((void**)&incl,   g_incl);
    cudaGetSymbolAddress((void**)&rowptr, g_rowptr);
    cudaGetSymbolAddress((void**)&cursor, g_cursor);
    cudaGetSymbolAddress((void**)&col,    g_col);
    cudaGetSymbolAddress((void**)&bsum,   g_bsum);

    const int NB_N   = (NN + 255) / 256;
    const int NB_E   = (EE + 255) / 256;
    const int NB_SC  = (NN + 1023) / 1024;
    const int GB     = (NN + 127) / 128;
    const int NB_GAT = (NN * 32 + 255) / 256;

    // --- graph preprocessing ---
    k_init_deg<<<NB_N, 256>>>(deg);
    k_count<<<NB_E, 256>>>(ei, deg);
    k_scan_block<<<NB_SC, 1024>>>(deg, incl, bsum);
    k_finalize<<<NB_N, 256>>>(deg, incl, bsum, rowptr, cursor, dinv);
    k_fill<<<NB_E, 256>>>(ei, cursor, col);

    // --- transpose + fp16-convert all weights ---
    k_transpose_all<<<96, 256>>>(enc_w1, enc_w2, w_c1, w_c2, w_c3, dec_w1, dec_w2, wth);

    const __half* wt_enc1 = wth + 0;
    const __half* wt_enc2 = wth + 8192;
    const __half* wt_c1   = wth + 24576;
    const __half* wt_c2   = wth + 40960;
    const __half* wt_c3   = wth + 57344;
    const __half* wt_dec1 = wth + 73728;
    const __half* wt_dec2 = wth + 90112;

    // --- encoder MLP ---
    k_hmma<64, 128, M_RELU, false, true><<<GB, 256>>>(x,   wt_enc1, enc_b1, nullptr, hb0);
    k_hmma<128, 128, M_BIAS, true, true><<<GB, 256>>>(hb0, wt_enc2, enc_b2, nullptr, hb1);

    // --- GCN conv 1 ---
    k_hmma<128, 128, M_DINV, true, true><<<GB, 256>>>(hb1, wt_c1, nullptr, dinv, hb2);
    k_gather_h<<<NB_GAT, 256>>>(hb2, rowptr, col, dinv, b_c1, hb0);

    // --- GCN conv 2 ---
    k_hmma<128, 128, M_DINV, true, true><<<GB, 256>>>(hb0, wt_c2, nullptr, dinv, hb2);
    k_gather_h<<<NB_GAT, 256>>>(hb2, rowptr, col, dinv, b_c2, hb1);

    // --- GCN conv 3 ---
    k_hmma<128, 128, M_DINV, true, true><<<GB, 256>>>(hb1, wt_c3, nullptr, dinv, hb2);
    k_gather_h<<<NB_GAT, 256>>>(hb2, rowptr, col, dinv, b_c3, hb0);

    // --- decoder MLP + sigmoid ---
    k_hmma<128, 128, M_RELU, true, true><<<GB, 256>>>(hb0, wt_dec1, dec_b1, nullptr, hb1);
    k_hmma<128, 64, M_SIG, true, false><<<GB, 256>>>(hb1, wt_dec2, dec_b2, nullptr, out);
}

// round 7
// speedup vs baseline: 3.1617x; 1.0477x over previous
#include <cuda_runtime.h>
#include <cuda_fp16.h>
#include <math.h>
#include <stdint.h>

#define NN 50000
#define EE 800000
#define FF 64
#define HH 128

#define M_RELU 0
#define M_BIAS 1
#define M_DINV 2
#define M_SIG  3

// ---------------- scratch (no allocations allowed) ----------------
__device__ __half g_hb0[NN * HH];
__device__ __half g_hb1[NN * HH];
__device__ __half g_hb2[NN * HH];
__device__ __half g_wth[98304];     // transposed fp16 weights
__device__ float  g_dinv[NN];
__device__ int    g_deg[NN];
__device__ int    g_incl[NN];
__device__ int    g_rowptr[NN + 1];
__device__ int    g_cursor[NN];
__device__ int    g_col[EE];
__device__ int    g_bsum[64];

// ---------------- graph preprocessing ----------------
__global__ void k_count(const int* __restrict__ ei, int* deg) {
    int e = blockIdx.x * blockDim.x + threadIdx.x;
    if (e < EE) atomicAdd(&deg[ei[EE + e]], 1);
}

__global__ void k_scan_block(const int* __restrict__ deg, int* incl, int* bsum) {
    __shared__ int s[1024];
    int i = blockIdx.x * 1024 + threadIdx.x;
    s[threadIdx.x] = (i < NN) ? deg[i] : 0;
    __syncthreads();
    for (int off = 1; off < 1024; off <<= 1) {
        int t = (threadIdx.x >= off) ? s[threadIdx.x - off] : 0;
        __syncthreads();
        s[threadIdx.x] += t;
        __syncthreads();
    }
    if (i < NN) incl[i] = s[threadIdx.x];
    if (threadIdx.x == 1023) bsum[blockIdx.x] = s[1023];
}

__global__ void k_finalize(const int* __restrict__ deg, const int* __restrict__ incl,
                           const int* __restrict__ bsum,
                           int* rowptr, int* cursor, float* dinv) {
    __shared__ int sb[64];
    if (threadIdx.x < 49) sb[threadIdx.x] = bsum[threadIdx.x];
    __syncthreads();
    int i = blockIdx.x * blockDim.x + threadIdx.x;
    if (i >= NN) return;
    int blk = i >> 10;
    int off = 0;
    for (int j = 0; j < blk; j++) off += sb[j];
    int inc = incl[i] + off;
    int exc = inc - deg[i];
    rowptr[i] = exc;
    cursor[i] = exc;
    if (i == NN - 1) rowptr[NN] = inc;
    dinv[i] = rsqrtf((float)deg[i] + 1.0f);
}

__global__ void k_fill(const int* __restrict__ ei, int* cursor, int* col) {
    int e = blockIdx.x * blockDim.x + threadIdx.x;
    if (e >= EE) return;
    int s = ei[e];
    int d = ei[EE + e];
    int pos = atomicAdd(&cursor[d], 1);
    col[pos] = s;
}

// ---------------- weight transpose+convert: W[K,N] f32 -> WT[N,K] f16 ----------------
__global__ void k_transpose_all(const float* w0, const float* w1, const float* w2,
                                const float* w3, const float* w4, const float* w5,
                                const float* w6, __half* wt) {
    __shared__ float tile[32][33];
    int b = blockIdx.x;
    int m, local;
    if (b < 8)       { m = 0; local = b; }
    else if (b < 88) { m = 1 + (b - 8) / 16; local = (b - 8) % 16; }
    else             { m = 6; local = b - 88; }
    const float* srcs[7] = {w0, w1, w2, w3, w4, w5, w6};
    const int Rs[7]   = {64, 128, 128, 128, 128, 128, 128};
    const int Cs[7]   = {128, 128, 128, 128, 128, 128, 64};
    const int offs[7] = {0, 8192, 24576, 40960, 57344, 73728, 90112};
    const float* src = srcs[m];
    __half* dst = wt + offs[m];
    int R = Rs[m], C = Cs[m];
    int ct = C / 32;
    int tr = local / ct, tc = local % ct;
    int x = threadIdx.x % 32;
    int y0 = threadIdx.x / 32;
    for (int y = y0; y < 32; y += 8)
        tile[y][x] = src[(tr * 32 + y) * C + tc * 32 + x];
    __syncthreads();
    for (int y = y0; y < 32; y += 8)
        dst[(tc * 32 + y) * R + tr * 32 + x] = __float2half(tile[x][y]);
}

// ---------------- fp16 MMA helper ----------------
__device__ __forceinline__ void mma_f16(float* d, const uint32_t* a, uint32_t b0, uint32_t b1) {
    asm volatile(
        "mma.sync.aligned.m16n8k16.row.col.f32.f16.f16.f32 "
        "{%0,%1,%2,%3}, {%4,%5,%6,%7}, {%8,%9}, {%0,%1,%2,%3};"
        : "+f"(d[0]), "+f"(d[1]), "+f"(d[2]), "+f"(d[3])
        : "r"(a[0]), "r"(a[1]), "r"(a[2]), "r"(a[3]), "r"(b0), "r"(b1));
}

// ---------------- single fp16 warp-MMA GEMM (used for the 3 conv GEMMs) ----------------
template <int K, int NC, int MODE, bool AH, bool HOUT>
__global__ void __launch_bounds__(256)
k_hmma(const void* __restrict__ Av, const __half* __restrict__ WT,
       const float* __restrict__ bias, const float* __restrict__ dinv,
       void* __restrict__ Cv) {
    constexpr int BM = 128, BK = 64, PADH = BK + 8;
    constexpr int WNT = NC / 16;

    __shared__ __half As[BM * PADH];
    __shared__ __half Bs[NC * PADH];

    const int tid = threadIdx.x;
    const int lane = tid & 31;
    const int wid = tid >> 5;
    const int warp_m = (wid & 3) * 32;
    const int warp_n = (wid >> 2) * (NC / 2);
    const int gid = lane >> 2;
    const int tig = lane & 3;
    const int row0 = blockIdx.x * BM;

    const __half* Ah = (const __half*)Av;
    const float*  Af = (const float*)Av;

    float acc[2][WNT][4];
#pragma unroll
    for (int mt = 0; mt < 2; mt++)
#pragma unroll
        for (int nt = 0; nt < WNT; nt++)
#pragma unroll
            for (int r = 0; r < 4; r++) acc[mt][nt][r] = 0.0f;

    for (int kk = 0; kk < K; kk += BK) {
#pragma unroll
        for (int i = tid; i < BM * (BK / 8); i += 256) {
            int r = i / (BK / 8), c8 = i % (BK / 8);
            uint4 u = make_uint4(0, 0, 0, 0);
            if (row0 + r < NN) {
                if (AH) {
                    u = *(const uint4*)&Ah[(size_t)(row0 + r) * K + kk + c8 * 8];
                } else {
                    float4 f0 = *(const float4*)&Af[(size_t)(row0 + r) * K + kk + c8 * 8];
                    float4 f1 = *(const float4*)&Af[(size_t)(row0 + r) * K + kk + c8 * 8 + 4];
                    __half2 h0 = __floats2half2_rn(f0.x, f0.y);
                    __half2 h1 = __floats2half2_rn(f0.z, f0.w);
                    __half2 h2 = __floats2half2_rn(f1.x, f1.y);
                    __half2 h3 = __floats2half2_rn(f1.z, f1.w);
                    u.x = *(uint32_t*)&h0; u.y = *(uint32_t*)&h1;
                    u.z = *(uint32_t*)&h2; u.w = *(uint32_t*)&h3;
                }
            }
            *(uint4*)&As[r * PADH + c8 * 8] = u;
        }
#pragma unroll
        for (int i = tid; i < NC * (BK / 8); i += 256) {
            int n = i / (BK / 8), c8 = i % (BK / 8);
            *(uint4*)&Bs[n * PADH + c8 * 8] =
                *(const uint4*)&WT[(size_t)n * K + kk + c8 * 8];
        }
        __syncthreads();

#pragma unroll
        for (int ks = 0; ks < BK; ks += 16) {
            uint32_t a[2][4];
#pragma unroll
            for (int mt = 0; mt < 2; mt++) {
                int r = warp_m + mt * 16 + gid;
                a[mt][0] = *(const uint32_t*)&As[r * PADH + ks + 2 * tig];
                a[mt][1] = *(const uint32_t*)&As[(r + 8) * PADH + ks + 2 * tig];
                a[mt][2] = *(const uint32_t*)&As[r * PADH + ks + 2 * tig + 8];
                a[mt][3] = *(const uint32_t*)&As[(r + 8) * PADH + ks + 2 * tig + 8];
            }
#pragma unroll
            for (int nt = 0; nt < WNT; nt++) {
                int c = warp_n + nt * 8 + gid;
                uint32_t b0 = *(const uint32_t*)&Bs[c * PADH + ks + 2 * tig];
                uint32_t b1 = *(const uint32_t*)&Bs[c * PADH + ks + 2 * tig + 8];
#pragma unroll
                for (int mt = 0; mt < 2; mt++) mma_f16(acc[mt][nt], a[mt], b0, b1);
            }
        }
        __syncthreads();
    }

    float*   Cf = (float*)Cv;
    __half2* Ch = (__half2*)Cv;

#pragma unroll
    for (int mt = 0; mt < 2; mt++) {
#pragma unroll
        for (int half = 0; half < 2; half++) {
            int gr = row0 + warp_m + mt * 16 + gid + half * 8;
            if (gr >= NN) continue;
            float dn = (MODE == M_DINV) ? dinv[gr] : 0.0f;
#pragma unroll
            for (int nt = 0; nt < WNT; nt++) {
                int gc = warp_n + nt * 8 + tig * 2;
                float v0 = acc[mt][nt][half * 2 + 0];
                float v1 = acc[mt][nt][half * 2 + 1];
                if (MODE == M_DINV) {
                    v0 *= dn; v1 *= dn;
                } else {
                    float2 bb = *(const float2*)&bias[gc];
                    v0 += bb.x; v1 += bb.y;
                    if (MODE == M_RELU) { v0 = fmaxf(v0, 0.f); v1 = fmaxf(v1, 0.f); }
                    else if (MODE == M_SIG) {
                        v0 = 1.0f / (1.0f + expf(-v0));
                        v1 = 1.0f / (1.0f + expf(-v1));
                    }
                }
                if (HOUT) {
                    Ch[(size_t)gr * (NC / 2) + (gc >> 1)] = __floats2half2_rn(v0, v1);
                } else {
                    *(float2*)&Cf[(size_t)gr * NC + gc] = make_float2(v0, v1);
                }
            }
        }
    }
}

// ---------------- fused 2-layer MLP: out = MODE2(relu(A@W1T^T + b1) @ W2T^T + b2) ----------------
// GEMM1: [128, K1] @ [K1, 128] -> relu -> Hs (fp16 smem). GEMM2: Hs @ [128, NC2].
template <int K1, int NC2, int MODE2, bool AH, bool HOUT2>
__global__ void __launch_bounds__(256, 2)
k_mlp2(const void* __restrict__ Av, const __half* __restrict__ W1T,
       const float* __restrict__ b1, const __half* __restrict__ W2T,
       const float* __restrict__ b2, void* __restrict__ Cv) {
    constexpr int BM = 128, BK = 64, PADH = 72, PADH2 = 136;
    constexpr int WNT1 = 8;               // GEMM1: NC1=128, warp covers 64 cols
    constexpr int WNT2 = (NC2 / 2) / 8;   // 8 (NC2=128) or 4 (NC2=64)

    extern __shared__ __half sm[];
    __half* As  = sm;                     // 128*72   = 9216 halves
    __half* Bs  = sm + 9216;              // 128*72   = 9216
    __half* Hs  = sm + 18432;             // 128*136  = 17408
    __half* W2s = sm + 35840;             // NC2*136

    const int tid = threadIdx.x;
    const int lane = tid & 31;
    const int wid = tid >> 5;
    const int warp_m = (wid & 3) * 32;
    const int warp_n = (wid >> 2) * 64;          // GEMM1 N split
    const int warp_n2 = (wid >> 2) * (NC2 / 2);  // GEMM2 N split
    const int gid = lane >> 2;
    const int tig = lane & 3;
    const int row0 = blockIdx.x * BM;

    const __half* Ah = (const __half*)Av;
    const float*  Af = (const float*)Av;

    // stage W2T [NC2, 128] once
#pragma unroll
    for (int i = tid; i < NC2 * 16; i += 256) {
        int n = i / 16, c8 = i % 16;
        *(uint4*)&W2s[n * PADH2 + c8 * 8] = *(const uint4*)&W2T[(size_t)n * 128 + c8 * 8];
    }

    // ---- GEMM1 ----
    float acc[2][WNT1][4];
#pragma unroll
    for (int mt = 0; mt < 2; mt++)
#pragma unroll
        for (int nt = 0; nt < WNT1; nt++)
#pragma unroll
            for (int r = 0; r < 4; r++) acc[mt][nt][r] = 0.0f;

    for (int kk = 0; kk < K1; kk += BK) {
#pragma unroll
        for (int i = tid; i < BM * (BK / 8); i += 256) {
            int r = i / (BK / 8), c8 = i % (BK / 8);
            uint4 u = make_uint4(0, 0, 0, 0);
            if (row0 + r < NN) {
                if (AH) {
                    u = *(const uint4*)&Ah[(size_t)(row0 + r) * K1 + kk + c8 * 8];
                } else {
                    float4 f0 = *(const float4*)&Af[(size_t)(row0 + r) * K1 + kk + c8 * 8];
                    float4 f1 = *(const float4*)&Af[(size_t)(row0 + r) * K1 + kk + c8 * 8 + 4];
                    __half2 h0 = __floats2half2_rn(f0.x, f0.y);
                    __half2 h1 = __floats2half2_rn(f0.z, f0.w);
                    __half2 h2 = __floats2half2_rn(f1.x, f1.y);
                    __half2 h3 = __floats2half2_rn(f1.z, f1.w);
                    u.x = *(uint32_t*)&h0; u.y = *(uint32_t*)&h1;
                    u.z = *(uint32_t*)&h2; u.w = *(uint32_t*)&h3;
                }
            }
            *(uint4*)&As[r * PADH + c8 * 8] = u;
        }
#pragma unroll
        for (int i = tid; i < 128 * (BK / 8); i += 256) {
            int n = i / (BK / 8), c8 = i % (BK / 8);
            *(uint4*)&Bs[n * PADH + c8 * 8] =
                *(const uint4*)&W1T[(size_t)n * K1 + kk + c8 * 8];
        }
        __syncthreads();

#pragma unroll
        for (int ks = 0; ks < BK; ks += 16) {
            uint32_t a[2][4];
#pragma unroll
            for (int mt = 0; mt < 2; mt++) {
                int r = warp_m + mt * 16 + gid;
                a[mt][0] = *(const uint32_t*)&As[r * PADH + ks + 2 * tig];
                a[mt][1] = *(const uint32_t*)&As[(r + 8) * PADH + ks + 2 * tig];
                a[mt][2] = *(const uint32_t*)&As[r * PADH + ks + 2 * tig + 8];
                a[mt][3] = *(const uint32_t*)&As[(r + 8) * PADH + ks + 2 * tig + 8];
            }
#pragma unroll
            for (int nt = 0; nt < WNT1; nt++) {
                int c = warp_n + nt * 8 + gid;
                uint32_t b0 = *(const uint32_t*)&Bs[c * PADH + ks + 2 * tig];
                uint32_t b1 = *(const uint32_t*)&Bs[c * PADH + ks + 2 * tig + 8];
#pragma unroll
                for (int mt = 0; mt < 2; mt++) mma_f16(acc[mt][nt], a[mt], b0, b1);
            }
        }
        __syncthreads();
    }

    // epilogue1: relu(acc + b1) -> Hs fp16
#pragma unroll
    for (int mt = 0; mt < 2; mt++) {
#pragma unroll
        for (int half = 0; half < 2; half++) {
            int rloc = warp_m + mt * 16 + gid + half * 8;
#pragma unroll
            for (int nt = 0; nt < WNT1; nt++) {
                int gc = warp_n + nt * 8 + tig * 2;
                float2 bb = *(const float2*)&b1[gc];
                float v0 = fmaxf(acc[mt][nt][half * 2 + 0] + bb.x, 0.f);
                float v1 = fmaxf(acc[mt][nt][half * 2 + 1] + bb.y, 0.f);
                *(__half2*)&Hs[rloc * PADH2 + gc] = __floats2half2_rn(v0, v1);
            }
        }
    }
    __syncthreads();

    // ---- GEMM2: Hs [128,128] @ W2s^T ----
    float acc2[2][WNT2][4];
#pragma unroll
    for (int mt = 0; mt < 2; mt++)
#pragma unroll
        for (int nt = 0; nt < WNT2; nt++)
#pragma unroll
            for (int r = 0; r < 4; r++) acc2[mt][nt][r] = 0.0f;

#pragma unroll
    for (int ks = 0; ks < 128; ks += 16) {
        uint32_t a[2][4];
#pragma unroll
        for (int mt = 0; mt < 2; mt++) {
            int r = warp_m + mt * 16 + gid;
            a[mt][0] = *(const uint32_t*)&Hs[r * PADH2 + ks + 2 * tig];
            a[mt][1] = *(const uint32_t*)&Hs[(r + 8) * PADH2 + ks + 2 * tig];
            a[mt][2] = *(const uint32_t*)&Hs[r * PADH2 + ks + 2 * tig + 8];
            a[mt][3] = *(const uint32_t*)&Hs[(r + 8) * PADH2 + ks + 2 * tig + 8];
        }
#pragma unroll
        for (int nt = 0; nt < WNT2; nt++) {
            int c = warp_n2 + nt * 8 + gid;
            uint32_t b0 = *(const uint32_t*)&W2s[c * PADH2 + ks + 2 * tig];
            uint32_t b1 = *(const uint32_t*)&W2s[c * PADH2 + ks + 2 * tig + 8];
#pragma unroll
            for (int mt = 0; mt < 2; mt++) mma_f16(acc2[mt][nt], a[mt], b0, b1);
        }
    }

    // epilogue2
    float*   Cf = (float*)Cv;
    __half2* Ch = (__half2*)Cv;
#pragma unroll
    for (int mt = 0; mt < 2; mt++) {
#pragma unroll
        for (int half = 0; half < 2; half++) {
            int gr = row0 + warp_m + mt * 16 + gid + half * 8;
            if (gr >= NN) continue;
#pragma unroll
            for (int nt = 0; nt < WNT2; nt++) {
                int gc = warp_n2 + nt * 8 + tig * 2;
                float2 bb = *(const float2*)&b2[gc];
                float v0 = acc2[mt][nt][half * 2 + 0] + bb.x;
                float v1 = acc2[mt][nt][half * 2 + 1] + bb.y;
                if (MODE2 == M_SIG) {
                    v0 = 1.0f / (1.0f + expf(-v0));
                    v1 = 1.0f / (1.0f + expf(-v1));
                }
                if (HOUT2) {
                    Ch[(size_t)gr * (NC2 / 2) + (gc >> 1)] = __floats2half2_rn(v0, v1);
                } else {
                    *(float2*)&Cf[(size_t)gr * NC2 + gc] = make_float2(v0, v1);
                }
            }
        }
    }
}

// ---------------- CSR gather-aggregate over fp16 rows, fp16 out ----------------
__global__ void k_gather_h(const __half* __restrict__ hws, const int* __restrict__ rowptr,
                           const int* __restrict__ col, const float* __restrict__ dinv,
                           const float* __restrict__ bias, __half* __restrict__ out) {
    int gw = (blockIdx.x * blockDim.x + threadIdx.x) >> 5;
    if (gw >= NN) return;
    int lane = threadIdx.x & 31;
    const uint2* base = (const uint2*)hws;

    uint2 s = base[(size_t)gw * 32 + lane];  // self-loop
    float2 f0 = __half22float2(*(const __half2*)&s.x);
    float2 f1 = __half22float2(*(const __half2*)&s.y);
    float a0 = f0.x, a1 = f0.y, a2 = f1.x, a3 = f1.y;
    float c0 = 0.f, c1 = 0.f, c2 = 0.f, c3 = 0.f;

    int p = rowptr[gw];
    int p1 = rowptr[gw + 1];
    for (; p + 1 < p1; p += 2) {
        int s0 = col[p];
        int s1 = col[p + 1];
        uint2 v0 = base[(size_t)s0 * 32 + lane];
        uint2 v1 = base[(size_t)s1 * 32 + lane];
        float2 g0 = __half22float2(*(const __half2*)&v0.x);
        float2 g1 = __half22float2(*(const __half2*)&v0.y);
        float2 h0 = __half22float2(*(const __half2*)&v1.x);
        float2 h1 = __half22float2(*(const __half2*)&v1.y);
        a0 += g0.x; a1 += g0.y; a2 += g1.x; a3 += g1.y;
        c0 += h0.x; c1 += h0.y; c2 += h1.x; c3 += h1.y;
    }
    if (p < p1) {
        uint2 v = base[(size_t)col[p] * 32 + lane];
        float2 g0 = __half22float2(*(const __half2*)&v.x);
        float2 g1 = __half22float2(*(const __half2*)&v.y);
        a0 += g0.x; a1 += g0.y; a2 += g1.x; a3 += g1.y;
    }
    a0 += c0; a1 += c1; a2 += c2; a3 += c3;

    float dn = dinv[gw];
    float4 b = ((const float4*)bias)[lane];
    float o0 = fmaxf(fmaf(dn, a0, b.x), 0.f);
    float o1 = fmaxf(fmaf(dn, a1, b.y), 0.f);
    float o2 = fmaxf(fmaf(dn, a2, b.z), 0.f);
    float o3 = fmaxf(fmaf(dn, a3, b.w), 0.f);
    __half2 h0 = __floats2half2_rn(o0, o1);
    __half2 h1 = __floats2half2_rn(o2, o3);
    uint2 w;
    w.x = *(uint32_t*)&h0;
    w.y = *(uint32_t*)&h1;
    ((uint2*)out)[(size_t)gw * 32 + lane] = w;
}

// ---------------- host launcher ----------------
extern "C" void kernel_launch(void* const* d_in, const int* in_sizes, int n_in,
                              void* d_out, int out_size) {
    const float* x      = (const float*)d_in[0];
    const int*   ei     = (const int*)d_in[1];
    const float* enc_w1 = (const float*)d_in[2];
    const float* enc_b1 = (const float*)d_in[3];
    const float* enc_w2 = (const float*)d_in[4];
    const float* enc_b2 = (const float*)d_in[5];
    const float* w_c1   = (const float*)d_in[6];
    const float* b_c1   = (const float*)d_in[7];
    const float* w_c2   = (const float*)d_in[8];
    const float* b_c2   = (const float*)d_in[9];
    const float* w_c3   = (const float*)d_in[10];
    const float* b_c3   = (const float*)d_in[11];
    const float* dec_w1 = (const float*)d_in[12];
    const float* dec_b1 = (const float*)d_in[13];
    const float* dec_w2 = (const float*)d_in[14];
    const float* dec_b2 = (const float*)d_in[15];
    float* out = (float*)d_out;

    __half *hb0, *hb1, *hb2, *wth;
    float *dinv;
    int *deg, *incl, *rowptr, *cursor, *col, *bsum;
    cudaGetSymbolAddress((void**)&hb0,    g_hb0);
    cudaGetSymbolAddress((void**)&hb1,    g_hb1);
    cudaGetSymbolAddress((void**)&hb2,    g_hb2);
    cudaGetSymbolAddress((void**)&wth,    g_wth);
    cudaGetSymbolAddress((void**)&dinv,   g_dinv);
    cudaGetSymbolAddress((void**)&deg,    g_deg);
    cudaGetSymbolAddress((void**)&incl,   g_incl);
    cudaGetSymbolAddress((void**)&rowptr, g_rowptr);
    cudaGetSymbolAddress((void**)&cursor, g_cursor);
    cudaGetSymbolAddress((void**)&col,    g_col);
    cudaGetSymbolAddress((void**)&bsum,   g_bsum);

    const int NB_E   = (EE + 255) / 256;
    const int NB_N   = (NN + 255) / 256;
    const int NB_SC  = (NN + 1023) / 1024;
    const int GB     = (NN + 127) / 128;
    const int NB_GAT = (NN * 32 + 255) / 256;

    // fused MLP dynamic smem: (9216 + 9216 + 17408 + NC2*136) halves * 2B
    const int SM_ENC = (9216 + 9216 + 17408 + 128 * 136) * 2;  // 106496
    const int SM_DEC = (9216 + 9216 + 17408 + 64 * 136) * 2;   //  89088
    cudaFuncSetAttribute(k_mlp2<64, 128, M_BIAS, false, true>,
                         cudaFuncAttributeMaxDynamicSharedMemorySize, SM_ENC);
    cudaFuncSetAttribute(k_mlp2<128, 64, M_SIG, true, false>,
                         cudaFuncAttributeMaxDynamicSharedMemorySize, SM_DEC);

    // --- graph preprocessing ---
    cudaMemsetAsync(deg, 0, NN * sizeof(int));
    k_count<<<NB_E, 256>>>(ei, deg);
    k_scan_block<<<NB_SC, 1024>>>(deg, incl, bsum);
    k_finalize<<<NB_N, 256>>>(deg, incl, bsum, rowptr, cursor, dinv);
    k_fill<<<NB_E, 256>>>(ei, cursor, col);

    // --- transpose + fp16-convert all weights ---
    k_transpose_all<<<96, 256>>>(enc_w1, enc_w2, w_c1, w_c2, w_c3, dec_w1, dec_w2, wth);

    const __half* wt_enc1 = wth + 0;
    const __half* wt_enc2 = wth + 8192;
    const __half* wt_c1   = wth + 24576;
    const __half* wt_c2   = wth + 40960;
    const __half* wt_c3   = wth + 57344;
    const __half* wt_dec1 = wth + 73728;
    const __half* wt_dec2 = wth + 90112;

    // --- encoder MLP (fused) ---
    k_mlp2<64, 128, M_BIAS, false, true><<<GB, 256, SM_ENC>>>(
        x, wt_enc1, enc_b1, wt_enc2, enc_b2, hb1);

    // --- GCN conv 1 ---
    k_hmma<128, 128, M_DINV, true, true><<<GB, 256>>>(hb1, wt_c1, nullptr, dinv, hb2);
    k_gather_h<<<NB_GAT, 256>>>(hb2, rowptr, col, dinv, b_c1, hb0);

    // --- GCN conv 2 ---
    k_hmma<128, 128, M_DINV, true, true><<<GB, 256>>>(hb0, wt_c2, nullptr, dinv, hb2);
    k_gather_h<<<NB_GAT, 256>>>(hb2, rowptr, col, dinv, b_c2, hb1);

    // --- GCN conv 3 ---
    k_hmma<128, 128, M_DINV, true, true><<<GB, 256>>>(hb1, wt_c3, nullptr, dinv, hb2);
    k_gather_h<<<NB_GAT, 256>>>(hb2, rowptr, col, dinv, b_c3, hb0);

    // --- decoder MLP + sigmoid (fused) ---
    k_mlp2<128, 64, M_SIG, true, false><<<GB, 256, SM_DEC>>>(
        hb0, wt_dec1, dec_b1, wt_dec2, dec_b2, out);
}